// round 5
// baseline (speedup 1.0000x reference)
#include <cuda_runtime.h>
#include <cuda_bf16.h>
#include <math.h>

// Problem constants
#define BATCH   2
#define SEQ     2048
#define DMODEL  1024
#define NHEADS  16
#define DHEAD   64
#define MROWS   (BATCH * SEQ)          // 4096
#define QKVN    (3 * DMODEL)           // 3072

// Scratch (device globals: allocation-free rule)
__device__ float g_qkv[(size_t)MROWS * QKVN];
__device__ float g_att[(size_t)MROWS * DMODEL];
__device__ float g_xr [(size_t)MROWS * DMODEL];
__device__ float g_wir[(size_t)QKVN * DMODEL];
__device__ float g_wor[(size_t)DMODEL * DMODEL];

// ---------------------------------------------------------------------------
// helpers
// ---------------------------------------------------------------------------
__device__ __forceinline__ unsigned f2tf(float f) {
    unsigned r;
    asm("cvt.rna.tf32.f32 %0, %1;" : "=r"(r) : "f"(f));
    return r;
}
__device__ __forceinline__ float roundtf(float f) {
    return __uint_as_float(f2tf(f));
}
__device__ __forceinline__ void cp16(void* sdst, const void* gsrc) {
    unsigned s = (unsigned)__cvta_generic_to_shared(sdst);
    asm volatile("cp.async.cg.shared.global [%0], [%1], 16;" :: "r"(s), "l"(gsrc) : "memory");
}
#define CP_COMMIT()  asm volatile("cp.async.commit_group;" ::: "memory")
#define CP_WAIT0()   asm volatile("cp.async.wait_group 0;" ::: "memory")
#define CP_WAIT1()   asm volatile("cp.async.wait_group 1;" ::: "memory")

__device__ __forceinline__ void mma8(float c[4],
    unsigned a0, unsigned a1, unsigned a2, unsigned a3,
    unsigned b0, unsigned b1)
{
    asm volatile(
        "mma.sync.aligned.m16n8k8.row.col.f32.tf32.tf32.f32 "
        "{%0,%1,%2,%3}, {%4,%5,%6,%7}, {%8,%9}, {%0,%1,%2,%3};"
        : "+f"(c[0]), "+f"(c[1]), "+f"(c[2]), "+f"(c[3])
        : "r"(a0), "r"(a1), "r"(a2), "r"(a3), "r"(b0), "r"(b1));
}

// ---------------------------------------------------------------------------
// Pre-round fp32 -> tf32-representable fp32
// ---------------------------------------------------------------------------
__global__ void round_tf32_k(const float* __restrict__ s, float* __restrict__ d, int n4)
{
    int i = blockIdx.x * blockDim.x + threadIdx.x;
    if (i < n4) {
        float4 v = ((const float4*)s)[i];
        v.x = roundtf(v.x); v.y = roundtf(v.y);
        v.z = roundtf(v.z); v.w = roundtf(v.w);
        ((float4*)d)[i] = v;
    }
}

// ---------------------------------------------------------------------------
// GEMM (NT) tf32: C[M,N] = A[M,K] @ B[N,K]^T + bias[N]
// 128x128 block, BK=16, 128 threads (4 warps), warp tile 64x64.
// 3-stage cp.async pipeline, dynamic smem 61.4 KB.
// ---------------------------------------------------------------------------
#define GSTG (128 * 20)          // floats per stage per matrix
#define GEMM_SMEM (6 * GSTG * 4) // 61440 bytes

__global__ __launch_bounds__(128) void gemm_tf32(
    const float* __restrict__ A, const float* __restrict__ B,
    const float* __restrict__ bias, float* __restrict__ C,
    int M, int N, int K, int round_out)
{
    extern __shared__ __align__(16) float sm[];
    float* As = sm;              // [3][128][20]
    float* Bs = sm + 3 * GSTG;   // [3][128][20]

    const int tid  = threadIdx.x;
    const int warp = tid >> 5;
    const int lane = tid & 31;
    const int g    = lane >> 2;      // 0..7
    const int tg   = lane & 3;       // 0..3
    const int wm   = warp >> 1;      // 0..1  (m half)
    const int wn   = warp & 1;       // 0..1  (n half)

    const int m0 = blockIdx.y * 128;
    const int n0 = blockIdx.x * 128;

    float acc[4][8][4];
#pragma unroll
    for (int i = 0; i < 4; i++)
#pragma unroll
        for (int j = 0; j < 8; j++)
#pragma unroll
            for (int r = 0; r < 4; r++) acc[i][j][r] = 0.f;

    const int iters = K >> 4;

    // Issue loads for stage st at k-offset k0: 512 cp16 per matrix, 4/thread.
    // f = i*128+tid -> row r=f>>2 (0..127), kcol c4=(f&3)*4.
#define GEMM_ISSUE(st, k0)                                                     \
    {                                                                          \
        _Pragma("unroll")                                                      \
        for (int i = 0; i < 4; i++) {                                          \
            int f  = i * 128 + tid;                                            \
            int r  = f >> 2;                                                   \
            int c4 = (f & 3) << 2;                                             \
            cp16(&As[(st) * GSTG + r * 20 + c4],                               \
                 &A[(size_t)(m0 + r) * K + (k0) + c4]);                        \
            cp16(&Bs[(st) * GSTG + r * 20 + c4],                               \
                 &B[(size_t)(n0 + r) * K + (k0) + c4]);                        \
        }                                                                      \
        CP_COMMIT();                                                           \
    }

    GEMM_ISSUE(0, 0)
    if (iters > 1) GEMM_ISSUE(1, 16)

    int buf = 0;
    for (int it = 0; it < iters; it++) {
        if (it == iters - 1) { CP_WAIT0(); } else { CP_WAIT1(); }
        __syncthreads();   // stage `it` visible to all; buffer (it+2)%3 free

        if (it + 2 < iters) {
            int nst = buf + 2; if (nst >= 3) nst -= 3;
            GEMM_ISSUE(nst, (it + 2) << 4)
        }

        const float* Ab = &As[buf * GSTG];
        const float* Bb = &Bs[buf * GSTG];
#pragma unroll
        for (int ks = 0; ks < 2; ks++) {
            const int kk = ks * 8;
            unsigned a[4][4];
#pragma unroll
            for (int ma = 0; ma < 4; ma++) {
                int r = wm * 64 + ma * 16 + g;
                a[ma][0] = __float_as_uint(Ab[(r    ) * 20 + kk + tg]);
                a[ma][1] = __float_as_uint(Ab[(r + 8) * 20 + kk + tg]);
                a[ma][2] = __float_as_uint(Ab[(r    ) * 20 + kk + tg + 4]);
                a[ma][3] = __float_as_uint(Ab[(r + 8) * 20 + kk + tg + 4]);
            }
            unsigned b[8][2];
#pragma unroll
            for (int na = 0; na < 8; na++) {
                int n = wn * 64 + na * 8 + g;
                b[na][0] = __float_as_uint(Bb[n * 20 + kk + tg]);
                b[na][1] = __float_as_uint(Bb[n * 20 + kk + tg + 4]);
            }
#pragma unroll
            for (int ma = 0; ma < 4; ma++)
#pragma unroll
                for (int na = 0; na < 8; na++)
                    mma8(acc[ma][na], a[ma][0], a[ma][1], a[ma][2], a[ma][3],
                         b[na][0], b[na][1]);
        }
        buf = (buf + 1 == 3) ? 0 : buf + 1;
    }

    // Epilogue
#pragma unroll
    for (int ma = 0; ma < 4; ma++) {
        int row0 = m0 + wm * 64 + ma * 16 + g;
#pragma unroll
        for (int na = 0; na < 8; na++) {
            int col = n0 + wn * 64 + na * 8 + tg * 2;
            float2 bv = *(const float2*)&bias[col];
            float2 v0 = { acc[ma][na][0] + bv.x, acc[ma][na][1] + bv.y };
            float2 v1 = { acc[ma][na][2] + bv.x, acc[ma][na][3] + bv.y };
            if (round_out) {
                v0.x = roundtf(v0.x); v0.y = roundtf(v0.y);
                v1.x = roundtf(v1.x); v1.y = roundtf(v1.y);
            }
            *(float2*)&C[(size_t)row0 * N + col]       = v0;
            *(float2*)&C[(size_t)(row0 + 8) * N + col] = v1;
        }
    }
}

// ---------------------------------------------------------------------------
// Flash attention, tf32. Grid: (S/128, B*H). Block: 256 (8 warps).
// BQ=128 (warp w owns q-rows w*16..w*16+15), BK=32 double-buffered cp.async.
// Q fragments register-resident for the whole KV loop.
// Dynamic smem 54.3 KB. Output layout [B][H][S][Dh].
// ---------------------------------------------------------------------------
#define OFF_K   0            // [2][32][68]  -> 4352 floats
#define OFF_V   4352         // [2][32][72]  -> 4608 floats
#define OFF_P   8960         // [128][36]    -> 4608 floats
#define ATT_SMEM ((4352 + 4608 + 4608) * 4)   // 54272 bytes

__global__ __launch_bounds__(256) void attn_tf32(
    const float* __restrict__ qkv, float* __restrict__ outp)
{
    extern __shared__ __align__(16) float smf[];

    const int tid  = threadIdx.x;
    const int warp = tid >> 5;
    const int lane = tid & 31;
    const int g    = lane >> 2;
    const int tg   = lane & 3;
    const int wq0  = warp * 16;

    const int qt = blockIdx.x;
    const int bh = blockIdx.y;
    const int b  = bh >> 4;
    const int h  = bh & 15;

    const size_t rowbase = (size_t)b * SEQ * QKVN;
    const int qcol = h * DHEAD;
    const int kcol = DMODEL + h * DHEAD;
    const int vcol = 2 * DMODEL + h * DHEAD;
    const int q0   = qt * 128;

    // --- Stage Q tile (128x64) in smem scratch, pull fragments to registers ---
#pragma unroll
    for (int i = 0; i < 8; i++) {
        int f  = i * 256 + tid;
        int r  = f >> 4;
        int c4 = (f & 15) << 2;
        cp16(&smf[r * 68 + c4],
             &qkv[rowbase + (size_t)(q0 + r) * QKVN + qcol + c4]);
    }
    CP_COMMIT();
    CP_WAIT0();
    __syncthreads();

    unsigned qa[8][4];
#pragma unroll
    for (int ks = 0; ks < 8; ks++) {
        const int kk = ks * 8;
        qa[ks][0] = __float_as_uint(smf[(wq0 + g    ) * 68 + kk + tg]);
        qa[ks][1] = __float_as_uint(smf[(wq0 + g + 8) * 68 + kk + tg]);
        qa[ks][2] = __float_as_uint(smf[(wq0 + g    ) * 68 + kk + tg + 4]);
        qa[ks][3] = __float_as_uint(smf[(wq0 + g + 8) * 68 + kk + tg + 4]);
    }
    __syncthreads();   // Q reads done before K/V prefetch overwrites region

    float o[8][4];
#pragma unroll
    for (int i = 0; i < 8; i++)
#pragma unroll
        for (int j = 0; j < 4; j++) o[i][j] = 0.f;
    float mx0 = -INFINITY, mx1 = -INFINITY;
    float l0 = 0.f, l1 = 0.f;

    // K/V tile load: 32x64 each = 512 cp16 each, 2/thread each.
#define ATT_ISSUE(nb, k0g)                                                     \
    {                                                                          \
        _Pragma("unroll")                                                      \
        for (int i = 0; i < 2; i++) {                                          \
            int f  = i * 256 + tid;                                            \
            int r  = f >> 4;                                                   \
            int c4 = (f & 15) << 2;                                            \
            cp16(&smf[OFF_K + (nb) * 2176 + r * 68 + c4],                      \
                 &qkv[rowbase + (size_t)((k0g) + r) * QKVN + kcol + c4]);      \
            cp16(&smf[OFF_V + (nb) * 2304 + r * 72 + c4],                      \
                 &qkv[rowbase + (size_t)((k0g) + r) * QKVN + vcol + c4]);      \
        }                                                                      \
        CP_COMMIT();                                                           \
    }

    ATT_ISSUE(0, 0)

    const int NT = SEQ / 32;
    for (int t = 0; t < NT; t++) {
        const int buf = t & 1;
        const int kbase = OFF_K + buf * 2176;
        const int vbase = OFF_V + buf * 2304;

        if (t + 1 < NT) {
            ATT_ISSUE(buf ^ 1, (t + 1) * 32)
            CP_WAIT1();
        } else {
            CP_WAIT0();
        }
        __syncthreads();

        // --- Scores: S[16q x 32k] = Q @ K^T ---
        float s[4][4];
#pragma unroll
        for (int na = 0; na < 4; na++)
#pragma unroll
            for (int r = 0; r < 4; r++) s[na][r] = 0.f;

#pragma unroll
        for (int ks = 0; ks < 8; ks++) {
            const int kk = ks * 8;
#pragma unroll
            for (int na = 0; na < 4; na++) {
                unsigned b0 = __float_as_uint(smf[kbase + (na * 8 + g) * 68 + kk + tg]);
                unsigned b1 = __float_as_uint(smf[kbase + (na * 8 + g) * 68 + kk + tg + 4]);
                mma8(s[na], qa[ks][0], qa[ks][1], qa[ks][2], qa[ks][3], b0, b1);
            }
        }

        // --- Online softmax (rows g and g+8, quad shfl reduce) ---
        float t0 = -INFINITY, t1 = -INFINITY;
#pragma unroll
        for (int na = 0; na < 4; na++) {
            s[na][0] *= 0.125f; s[na][1] *= 0.125f;
            s[na][2] *= 0.125f; s[na][3] *= 0.125f;
            t0 = fmaxf(t0, fmaxf(s[na][0], s[na][1]));
            t1 = fmaxf(t1, fmaxf(s[na][2], s[na][3]));
        }
        t0 = fmaxf(t0, __shfl_xor_sync(0xffffffffu, t0, 1));
        t0 = fmaxf(t0, __shfl_xor_sync(0xffffffffu, t0, 2));
        t1 = fmaxf(t1, __shfl_xor_sync(0xffffffffu, t1, 1));
        t1 = fmaxf(t1, __shfl_xor_sync(0xffffffffu, t1, 2));

        float mn0 = fmaxf(mx0, t0), mn1 = fmaxf(mx1, t1);
        float corr0 = __expf(mx0 - mn0), corr1 = __expf(mx1 - mn1);

        float ls0 = 0.f, ls1 = 0.f;
#pragma unroll
        for (int na = 0; na < 4; na++) {
            float p0 = __expf(s[na][0] - mn0);
            float p1 = __expf(s[na][1] - mn0);
            float p2 = __expf(s[na][2] - mn1);
            float p3 = __expf(s[na][3] - mn1);
            ls0 += p0 + p1; ls1 += p2 + p3;
            int c = na * 8 + tg * 2;
            smf[OFF_P + (wq0 + g    ) * 36 + c    ] = __uint_as_float(f2tf(p0));
            smf[OFF_P + (wq0 + g    ) * 36 + c + 1] = __uint_as_float(f2tf(p1));
            smf[OFF_P + (wq0 + g + 8) * 36 + c    ] = __uint_as_float(f2tf(p2));
            smf[OFF_P + (wq0 + g + 8) * 36 + c + 1] = __uint_as_float(f2tf(p3));
        }
        ls0 += __shfl_xor_sync(0xffffffffu, ls0, 1);
        ls0 += __shfl_xor_sync(0xffffffffu, ls0, 2);
        ls1 += __shfl_xor_sync(0xffffffffu, ls1, 1);
        ls1 += __shfl_xor_sync(0xffffffffu, ls1, 2);
        l0 = l0 * corr0 + ls0;  mx0 = mn0;
        l1 = l1 * corr1 + ls1;  mx1 = mn1;

#pragma unroll
        for (int na = 0; na < 8; na++) {
            o[na][0] *= corr0; o[na][1] *= corr0;
            o[na][2] *= corr1; o[na][3] *= corr1;
        }

        __syncwarp();   // P rows warp-private: order STS -> LDS

        // --- PV: O[16q x 64d] += P[16 x 32] @ V[32 x 64] ---
#pragma unroll
        for (int ks = 0; ks < 4; ks++) {
            const int kk = ks * 8;
            unsigned a0 = __float_as_uint(smf[OFF_P + (wq0 + g    ) * 36 + kk + tg]);
            unsigned a1 = __float_as_uint(smf[OFF_P + (wq0 + g + 8) * 36 + kk + tg]);
            unsigned a2 = __float_as_uint(smf[OFF_P + (wq0 + g    ) * 36 + kk + tg + 4]);
            unsigned a3 = __float_as_uint(smf[OFF_P + (wq0 + g + 8) * 36 + kk + tg + 4]);
#pragma unroll
            for (int na = 0; na < 8; na++) {
                unsigned b0 = __float_as_uint(smf[vbase + (kk + tg    ) * 72 + na * 8 + g]);
                unsigned b1 = __float_as_uint(smf[vbase + (kk + tg + 4) * 72 + na * 8 + g]);
                mma8(o[na], a0, a1, a2, a3, b0, b1);
            }
        }
        __syncthreads();   // all warps done with buf before overwrite
    }

    // --- Finalize + store (rounded: feeds final tf32 GEMM) ---
    float inv0 = 1.0f / l0, inv1 = 1.0f / l1;
    int row0 = q0 + wq0 + g;
    size_t base0 = ((size_t)bh * SEQ + row0)     * DHEAD;
    size_t base1 = ((size_t)bh * SEQ + row0 + 8) * DHEAD;
#pragma unroll
    for (int na = 0; na < 8; na++) {
        int c = na * 8 + tg * 2;
        float2 v0 = { roundtf(o[na][0] * inv0), roundtf(o[na][1] * inv0) };
        float2 v1 = { roundtf(o[na][2] * inv1), roundtf(o[na][3] * inv1) };
        *(float2*)&outp[base0 + c] = v0;
        *(float2*)&outp[base1 + c] = v1;
    }
}

// ---------------------------------------------------------------------------
// Launch
// ---------------------------------------------------------------------------
extern "C" void kernel_launch(void* const* d_in, const int* in_sizes, int n_in,
                              void* d_out, int out_size)
{
    const float* x     = (const float*)d_in[0];
    const float* w_in  = (const float*)d_in[1];
    const float* b_in  = (const float*)d_in[2];
    const float* w_out = (const float*)d_in[3];
    const float* b_out = (const float*)d_in[4];
    float* out = (float*)d_out;

    float *qkv_p, *att_p, *xr_p, *wir_p, *wor_p;
    cudaGetSymbolAddress((void**)&qkv_p, g_qkv);
    cudaGetSymbolAddress((void**)&att_p, g_att);
    cudaGetSymbolAddress((void**)&xr_p,  g_xr);
    cudaGetSymbolAddress((void**)&wir_p, g_wir);
    cudaGetSymbolAddress((void**)&wor_p, g_wor);

    cudaFuncSetAttribute(gemm_tf32,
        cudaFuncAttributeMaxDynamicSharedMemorySize, GEMM_SMEM);
    cudaFuncSetAttribute(attn_tf32,
        cudaFuncAttributeMaxDynamicSharedMemorySize, ATT_SMEM);

    // 0) Round inputs to tf32-representable fp32
    {
        int n4x  = (MROWS * DMODEL) / 4;
        int n4wi = (QKVN * DMODEL) / 4;
        int n4wo = (DMODEL * DMODEL) / 4;
        round_tf32_k<<<(n4x  + 255) / 256, 256>>>(x,     xr_p,  n4x);
        round_tf32_k<<<(n4wi + 255) / 256, 256>>>(w_in,  wir_p, n4wi);
        round_tf32_k<<<(n4wo + 255) / 256, 256>>>(w_out, wor_p, n4wo);
    }
    // 1) QKV = x @ w_in^T + b_in (rounded epilogue)
    {
        dim3 grid(QKVN / 128, MROWS / 128);
        gemm_tf32<<<grid, 128, GEMM_SMEM>>>(xr_p, wir_p, b_in, qkv_p,
                                            MROWS, QKVN, DMODEL, 1);
    }
    // 2) attention -> g_att in [B][H][S][Dh]
    {
        dim3 grid(SEQ / 128, BATCH * NHEADS);
        attn_tf32<<<grid, 256, ATT_SMEM>>>(qkv_p, att_p);
    }
    // 3) out = att @ w_out^T + b_out
    {
        dim3 grid(DMODEL / 128, MROWS / 128);
        gemm_tf32<<<grid, 128, GEMM_SMEM>>>(att_p, wor_p, b_out, out,
                                            MROWS, DMODEL, DMODEL, 0);
    }
}

// round 10
// speedup vs baseline: 1.0701x; 1.0701x over previous
#include <cuda_runtime.h>
#include <cuda_bf16.h>
#include <math.h>
#include <stdint.h>

// Problem constants
#define BATCH   2
#define SEQ     2048
#define DMODEL  1024
#define NHEADS  16
#define DHEAD   64
#define MROWS   (BATCH * SEQ)          // 4096
#define QKVN    (3 * DMODEL)           // 3072

// Scratch (device globals: allocation-free rule)
__device__ float g_qkv[(size_t)MROWS * QKVN];
__device__ float g_att[(size_t)MROWS * DMODEL];
__device__ float g_xr [(size_t)MROWS * DMODEL];
__device__ float g_wir[(size_t)QKVN * DMODEL];
__device__ float g_wor[(size_t)DMODEL * DMODEL];

// ---------------------------------------------------------------------------
// helpers
// ---------------------------------------------------------------------------
__device__ __forceinline__ unsigned f2tf(float f) {
    unsigned r;
    asm("cvt.rna.tf32.f32 %0, %1;" : "=r"(r) : "f"(f));
    return r;
}
__device__ __forceinline__ float roundtf(float f) {
    return __uint_as_float(f2tf(f));
}
__device__ __forceinline__ void cp16(void* sdst, const void* gsrc) {
    unsigned s = (unsigned)__cvta_generic_to_shared(sdst);
    asm volatile("cp.async.cg.shared.global [%0], [%1], 16;" :: "r"(s), "l"(gsrc) : "memory");
}
#define CP_COMMIT()  asm volatile("cp.async.commit_group;" ::: "memory")
#define CP_WAIT0()   asm volatile("cp.async.wait_group 0;" ::: "memory")
#define CP_WAIT1()   asm volatile("cp.async.wait_group 1;" ::: "memory")

__device__ __forceinline__ void mma8(float c[4],
    unsigned a0, unsigned a1, unsigned a2, unsigned a3,
    unsigned b0, unsigned b1)
{
    asm volatile(
        "mma.sync.aligned.m16n8k8.row.col.f32.tf32.tf32.f32 "
        "{%0,%1,%2,%3}, {%4,%5,%6,%7}, {%8,%9}, {%0,%1,%2,%3};"
        : "+f"(c[0]), "+f"(c[1]), "+f"(c[2]), "+f"(c[3])
        : "r"(a0), "r"(a1), "r"(a2), "r"(a3), "r"(b0), "r"(b1));
}

// ---------------------------------------------------------------------------
// Pre-round fp32 -> tf32-representable fp32 (unbiased rna — load-bearing)
// ---------------------------------------------------------------------------
__global__ void round_tf32_k(const float* __restrict__ s, float* __restrict__ d, int n4)
{
    int i = blockIdx.x * blockDim.x + threadIdx.x;
    if (i < n4) {
        float4 v = ((const float4*)s)[i];
        v.x = roundtf(v.x); v.y = roundtf(v.y);
        v.z = roundtf(v.z); v.w = roundtf(v.w);
        ((float4*)d)[i] = v;
    }
}

// ---------------------------------------------------------------------------
// GEMM (NT) tf32 (PROVEN, R5): C[M,N] = A[M,K] @ B[N,K]^T + bias[N]
// 128x128 block, BK=16, 128 threads (4 warps), warp tile 64x64.
// 3-stage cp.async pipeline, dynamic smem 61.4 KB.
// ---------------------------------------------------------------------------
#define GSTG (128 * 20)          // floats per stage per matrix
#define GEMM_SMEM (6 * GSTG * 4) // 61440 bytes

__global__ __launch_bounds__(128) void gemm_tf32(
    const float* __restrict__ A, const float* __restrict__ B,
    const float* __restrict__ bias, float* __restrict__ C,
    int M, int N, int K, int round_out)
{
    extern __shared__ __align__(16) float sm[];
    float* As = sm;              // [3][128][20]
    float* Bs = sm + 3 * GSTG;   // [3][128][20]

    const int tid  = threadIdx.x;
    const int warp = tid >> 5;
    const int lane = tid & 31;
    const int g    = lane >> 2;
    const int tg   = lane & 3;
    const int wm   = warp >> 1;
    const int wn   = warp & 1;

    const int m0 = blockIdx.y * 128;
    const int n0 = blockIdx.x * 128;

    float acc[4][8][4];
#pragma unroll
    for (int i = 0; i < 4; i++)
#pragma unroll
        for (int j = 0; j < 8; j++)
#pragma unroll
            for (int r = 0; r < 4; r++) acc[i][j][r] = 0.f;

    const int iters = K >> 4;

#define GEMM_ISSUE(st, k0)                                                     \
    {                                                                          \
        _Pragma("unroll")                                                      \
        for (int i = 0; i < 4; i++) {                                          \
            int f  = i * 128 + tid;                                            \
            int r  = f >> 2;                                                   \
            int c4 = (f & 3) << 2;                                             \
            cp16(&As[(st) * GSTG + r * 20 + c4],                               \
                 &A[(size_t)(m0 + r) * K + (k0) + c4]);                        \
            cp16(&Bs[(st) * GSTG + r * 20 + c4],                               \
                 &B[(size_t)(n0 + r) * K + (k0) + c4]);                        \
        }                                                                      \
        CP_COMMIT();                                                           \
    }

    GEMM_ISSUE(0, 0)
    if (iters > 1) GEMM_ISSUE(1, 16)

    int buf = 0;
    for (int it = 0; it < iters; it++) {
        if (it == iters - 1) { CP_WAIT0(); } else { CP_WAIT1(); }
        __syncthreads();

        if (it + 2 < iters) {
            int nst = buf + 2; if (nst >= 3) nst -= 3;
            GEMM_ISSUE(nst, (it + 2) << 4)
        }

        const float* Ab = &As[buf * GSTG];
        const float* Bb = &Bs[buf * GSTG];
#pragma unroll
        for (int ks = 0; ks < 2; ks++) {
            const int kk = ks * 8;
            unsigned a[4][4];
#pragma unroll
            for (int ma = 0; ma < 4; ma++) {
                int r = wm * 64 + ma * 16 + g;
                a[ma][0] = __float_as_uint(Ab[(r    ) * 20 + kk + tg]);
                a[ma][1] = __float_as_uint(Ab[(r + 8) * 20 + kk + tg]);
                a[ma][2] = __float_as_uint(Ab[(r    ) * 20 + kk + tg + 4]);
                a[ma][3] = __float_as_uint(Ab[(r + 8) * 20 + kk + tg + 4]);
            }
            unsigned b[8][2];
#pragma unroll
            for (int na = 0; na < 8; na++) {
                int n = wn * 64 + na * 8 + g;
                b[na][0] = __float_as_uint(Bb[n * 20 + kk + tg]);
                b[na][1] = __float_as_uint(Bb[n * 20 + kk + tg + 4]);
            }
#pragma unroll
            for (int ma = 0; ma < 4; ma++)
#pragma unroll
                for (int na = 0; na < 8; na++)
                    mma8(acc[ma][na], a[ma][0], a[ma][1], a[ma][2], a[ma][3],
                         b[na][0], b[na][1]);
        }
        buf = (buf + 1 == 3) ? 0 : buf + 1;
    }

    // Epilogue
#pragma unroll
    for (int ma = 0; ma < 4; ma++) {
        int row0 = m0 + wm * 64 + ma * 16 + g;
#pragma unroll
        for (int na = 0; na < 8; na++) {
            int col = n0 + wn * 64 + na * 8 + tg * 2;
            float2 bv = *(const float2*)&bias[col];
            float2 v0 = { acc[ma][na][0] + bv.x, acc[ma][na][1] + bv.y };
            float2 v1 = { acc[ma][na][2] + bv.x, acc[ma][na][3] + bv.y };
            if (round_out) {
                v0.x = roundtf(v0.x); v0.y = roundtf(v0.y);
                v1.x = roundtf(v1.x); v1.y = roundtf(v1.y);
            }
            *(float2*)&C[(size_t)row0 * N + col]       = v0;
            *(float2*)&C[(size_t)(row0 + 8) * N + col] = v1;
        }
    }
}

// ---------------------------------------------------------------------------
// Flash attention, tf32 (PROVEN, R4). Grid: (S/64, B*H). Block: 128 (4 warps).
// BQ=64, BK=32 double-buffered cp.async. Q fragments register-resident.
// 44 KB static smem. Output fp32 (rounded) in [B][H][S][Dh] layout.
// ---------------------------------------------------------------------------
#define OFF_K   0            // [2][32][68]  -> 4352 floats
#define OFF_V   4352         // [2][32][72]  -> 4608 floats
#define OFF_P   8960         // [64][36]     -> 2304 floats
#define SM_FLT  11264        // 45056 bytes

__global__ __launch_bounds__(128) void attn_tf32(
    const float* __restrict__ qkv, float* __restrict__ outp)
{
    __shared__ __align__(16) float smf[SM_FLT];

    const int tid  = threadIdx.x;
    const int warp = tid >> 5;
    const int lane = tid & 31;
    const int g    = lane >> 2;
    const int tg   = lane & 3;
    const int wq0  = warp * 16;

    const int qt = blockIdx.x;
    const int bh = blockIdx.y;
    const int b  = bh >> 4;
    const int h  = bh & 15;

    const size_t rowbase = (size_t)b * SEQ * QKVN;
    const int qcol = h * DHEAD;
    const int kcol = DMODEL + h * DHEAD;
    const int vcol = 2 * DMODEL + h * DHEAD;
    const int q0   = qt * 64;

    // Stage Q tile (64x64) into smem scratch, pull fragments to registers.
#pragma unroll
    for (int i = 0; i < 8; i++) {
        int f  = i * 128 + tid;
        int r  = f >> 4;
        int c4 = (f & 15) << 2;
        cp16(&smf[r * 68 + c4],
             &qkv[rowbase + (size_t)(q0 + r) * QKVN + qcol + c4]);
    }
    CP_COMMIT();
    CP_WAIT0();
    __syncthreads();

    unsigned qa[8][4];
#pragma unroll
    for (int ks = 0; ks < 8; ks++) {
        const int kk = ks * 8;
        qa[ks][0] = __float_as_uint(smf[(wq0 + g    ) * 68 + kk + tg]);
        qa[ks][1] = __float_as_uint(smf[(wq0 + g + 8) * 68 + kk + tg]);
        qa[ks][2] = __float_as_uint(smf[(wq0 + g    ) * 68 + kk + tg + 4]);
        qa[ks][3] = __float_as_uint(smf[(wq0 + g + 8) * 68 + kk + tg + 4]);
    }
    __syncthreads();

    float o[8][4];
#pragma unroll
    for (int i = 0; i < 8; i++)
#pragma unroll
        for (int j = 0; j < 4; j++) o[i][j] = 0.f;
    float mx0 = -INFINITY, mx1 = -INFINITY;
    float l0 = 0.f, l1 = 0.f;

#define ATT_ISSUE(nb, k0g)                                                     \
    {                                                                          \
        _Pragma("unroll")                                                      \
        for (int i = 0; i < 4; i++) {                                          \
            int f  = i * 128 + tid;                                            \
            int r  = f >> 4;                                                   \
            int c4 = (f & 15) << 2;                                            \
            cp16(&smf[OFF_K + (nb) * 2176 + r * 68 + c4],                      \
                 &qkv[rowbase + (size_t)((k0g) + r) * QKVN + kcol + c4]);      \
            cp16(&smf[OFF_V + (nb) * 2304 + r * 72 + c4],                      \
                 &qkv[rowbase + (size_t)((k0g) + r) * QKVN + vcol + c4]);      \
        }                                                                      \
        CP_COMMIT();                                                           \
    }

    ATT_ISSUE(0, 0)

    const int NT = SEQ / 32;
    for (int t = 0; t < NT; t++) {
        const int buf = t & 1;
        const int kbase = OFF_K + buf * 2176;
        const int vbase = OFF_V + buf * 2304;

        if (t + 1 < NT) {
            ATT_ISSUE(buf ^ 1, (t + 1) * 32)
            CP_WAIT1();
        } else {
            CP_WAIT0();
        }
        __syncthreads();

        float s[4][4];
#pragma unroll
        for (int na = 0; na < 4; na++)
#pragma unroll
            for (int r = 0; r < 4; r++) s[na][r] = 0.f;

#pragma unroll
        for (int ks = 0; ks < 8; ks++) {
            const int kk = ks * 8;
#pragma unroll
            for (int na = 0; na < 4; na++) {
                unsigned b0 = __float_as_uint(smf[kbase + (na * 8 + g) * 68 + kk + tg]);
                unsigned b1 = __float_as_uint(smf[kbase + (na * 8 + g) * 68 + kk + tg + 4]);
                mma8(s[na], qa[ks][0], qa[ks][1], qa[ks][2], qa[ks][3], b0, b1);
            }
        }

        float t0 = -INFINITY, t1 = -INFINITY;
#pragma unroll
        for (int na = 0; na < 4; na++) {
            s[na][0] *= 0.125f; s[na][1] *= 0.125f;
            s[na][2] *= 0.125f; s[na][3] *= 0.125f;
            t0 = fmaxf(t0, fmaxf(s[na][0], s[na][1]));
            t1 = fmaxf(t1, fmaxf(s[na][2], s[na][3]));
        }
        t0 = fmaxf(t0, __shfl_xor_sync(0xffffffffu, t0, 1));
        t0 = fmaxf(t0, __shfl_xor_sync(0xffffffffu, t0, 2));
        t1 = fmaxf(t1, __shfl_xor_sync(0xffffffffu, t1, 1));
        t1 = fmaxf(t1, __shfl_xor_sync(0xffffffffu, t1, 2));

        float mn0 = fmaxf(mx0, t0), mn1 = fmaxf(mx1, t1);
        float corr0 = __expf(mx0 - mn0), corr1 = __expf(mx1 - mn1);

        float ls0 = 0.f, ls1 = 0.f;
#pragma unroll
        for (int na = 0; na < 4; na++) {
            float p0 = __expf(s[na][0] - mn0);
            float p1 = __expf(s[na][1] - mn0);
            float p2 = __expf(s[na][2] - mn1);
            float p3 = __expf(s[na][3] - mn1);
            ls0 += p0 + p1; ls1 += p2 + p3;
            int c = na * 8 + tg * 2;
            smf[OFF_P + (wq0 + g    ) * 36 + c    ] = __uint_as_float(f2tf(p0));
            smf[OFF_P + (wq0 + g    ) * 36 + c + 1] = __uint_as_float(f2tf(p1));
            smf[OFF_P + (wq0 + g + 8) * 36 + c    ] = __uint_as_float(f2tf(p2));
            smf[OFF_P + (wq0 + g + 8) * 36 + c + 1] = __uint_as_float(f2tf(p3));
        }
        ls0 += __shfl_xor_sync(0xffffffffu, ls0, 1);
        ls0 += __shfl_xor_sync(0xffffffffu, ls0, 2);
        ls1 += __shfl_xor_sync(0xffffffffu, ls1, 1);
        ls1 += __shfl_xor_sync(0xffffffffu, ls1, 2);
        l0 = l0 * corr0 + ls0;  mx0 = mn0;
        l1 = l1 * corr1 + ls1;  mx1 = mn1;

#pragma unroll
        for (int na = 0; na < 8; na++) {
            o[na][0] *= corr0; o[na][1] *= corr0;
            o[na][2] *= corr1; o[na][3] *= corr1;
        }

        __syncwarp();

#pragma unroll
        for (int ks = 0; ks < 4; ks++) {
            const int kk = ks * 8;
            unsigned a0 = __float_as_uint(smf[OFF_P + (wq0 + g    ) * 36 + kk + tg]);
            unsigned a1 = __float_as_uint(smf[OFF_P + (wq0 + g + 8) * 36 + kk + tg]);
            unsigned a2 = __float_as_uint(smf[OFF_P + (wq0 + g    ) * 36 + kk + tg + 4]);
            unsigned a3 = __float_as_uint(smf[OFF_P + (wq0 + g + 8) * 36 + kk + tg + 4]);
#pragma unroll
            for (int na = 0; na < 8; na++) {
                unsigned b0 = __float_as_uint(smf[vbase + (kk + tg    ) * 72 + na * 8 + g]);
                unsigned b1 = __float_as_uint(smf[vbase + (kk + tg + 4) * 72 + na * 8 + g]);
                mma8(o[na], a0, a1, a2, a3, b0, b1);
            }
        }
        __syncthreads();
    }

    float inv0 = 1.0f / l0, inv1 = 1.0f / l1;
    int row0 = q0 + wq0 + g;
    size_t base0 = ((size_t)bh * SEQ + row0)     * DHEAD;
    size_t base1 = ((size_t)bh * SEQ + row0 + 8) * DHEAD;
#pragma unroll
    for (int na = 0; na < 8; na++) {
        int c = na * 8 + tg * 2;
        float2 v0 = { roundtf(o[na][0] * inv0), roundtf(o[na][1] * inv0) };
        float2 v1 = { roundtf(o[na][2] * inv1), roundtf(o[na][3] * inv1) };
        *(float2*)&outp[base0 + c] = v0;
        *(float2*)&outp[base1 + c] = v1;
    }
}

// ---------------------------------------------------------------------------
// Launch
// ---------------------------------------------------------------------------
extern "C" void kernel_launch(void* const* d_in, const int* in_sizes, int n_in,
                              void* d_out, int out_size)
{
    const float* x     = (const float*)d_in[0];
    const float* w_in  = (const float*)d_in[1];
    const float* b_in  = (const float*)d_in[2];
    const float* w_out = (const float*)d_in[3];
    const float* b_out = (const float*)d_in[4];
    float* out = (float*)d_out;

    float *qkv_p, *att_p, *xr_p, *wir_p, *wor_p;
    cudaGetSymbolAddress((void**)&qkv_p, g_qkv);
    cudaGetSymbolAddress((void**)&att_p, g_att);
    cudaGetSymbolAddress((void**)&xr_p,  g_xr);
    cudaGetSymbolAddress((void**)&wir_p, g_wir);
    cudaGetSymbolAddress((void**)&wor_p, g_wor);

    cudaFuncSetAttribute(gemm_tf32,
        cudaFuncAttributeMaxDynamicSharedMemorySize, GEMM_SMEM);

    // 0) Round inputs to tf32-representable fp32 (unbiased rna)
    {
        int n4x  = (MROWS * DMODEL) / 4;
        int n4wi = (QKVN * DMODEL) / 4;
        int n4wo = (DMODEL * DMODEL) / 4;
        round_tf32_k<<<(n4x  + 255) / 256, 256>>>(x,     xr_p,  n4x);
        round_tf32_k<<<(n4wi + 255) / 256, 256>>>(w_in,  wir_p, n4wi);
        round_tf32_k<<<(n4wo + 255) / 256, 256>>>(w_out, wor_p, n4wo);
    }
    // 1) QKV = x @ w_in^T + b_in (rounded epilogue)
    {
        dim3 grid(QKVN / 128, MROWS / 128);
        gemm_tf32<<<grid, 128, GEMM_SMEM>>>(xr_p, wir_p, b_in, qkv_p,
                                            MROWS, QKVN, DMODEL, 1);
    }
    // 2) attention -> g_att in [B][H][S][Dh]
    {
        dim3 grid(SEQ / 64, BATCH * NHEADS);
        attn_tf32<<<grid, 128>>>(qkv_p, att_p);
    }
    // 3) out = att @ w_out^T + b_out
    {
        dim3 grid(DMODEL / 128, MROWS / 128);
        gemm_tf32<<<grid, 128, GEMM_SMEM>>>(att_p, wor_p, b_out, out,
                                            MROWS, DMODEL, DMODEL, 0);
    }
}

// round 11
// speedup vs baseline: 1.1359x; 1.0615x over previous
#include <cuda_runtime.h>
#include <cuda_bf16.h>
#include <math.h>
#include <stdint.h>

// Problem constants
#define BATCH   2
#define SEQ     2048
#define DMODEL  1024
#define NHEADS  16
#define DHEAD   64
#define MROWS   (BATCH * SEQ)          // 4096
#define QKVN    (3 * DMODEL)           // 3072

// Scratch (device globals: allocation-free rule)
// g_xr/g_wir/g_wor/g_att are stored K-PERMUTED (within each 8-k group:
// newk = 2*(k%4) + (k%8 >= 4)) so GEMM fragment pairs (k, k+4) are adjacent.
__device__ float g_qkv[(size_t)MROWS * QKVN];     // natural layout (attention input)
__device__ float g_att[(size_t)MROWS * DMODEL];   // permuted (GEMM3 A)
__device__ float g_xr [(size_t)MROWS * DMODEL];   // permuted
__device__ float g_wir[(size_t)QKVN * DMODEL];    // permuted
__device__ float g_wor[(size_t)DMODEL * DMODEL];  // permuted

// ---------------------------------------------------------------------------
// helpers
// ---------------------------------------------------------------------------
__device__ __forceinline__ unsigned f2tf(float f) {
    unsigned r;
    asm("cvt.rna.tf32.f32 %0, %1;" : "=r"(r) : "f"(f));
    return r;
}
__device__ __forceinline__ float roundtf(float f) {
    return __uint_as_float(f2tf(f));
}
__device__ __forceinline__ void cp16(void* sdst, const void* gsrc) {
    unsigned s = (unsigned)__cvta_generic_to_shared(sdst);
    asm volatile("cp.async.cg.shared.global [%0], [%1], 16;" :: "r"(s), "l"(gsrc) : "memory");
}
#define CP_COMMIT()  asm volatile("cp.async.commit_group;" ::: "memory")
#define CP_WAIT0()   asm volatile("cp.async.wait_group 0;" ::: "memory")
#define CP_WAIT1()   asm volatile("cp.async.wait_group 1;" ::: "memory")

__device__ __forceinline__ void mma8(float c[4],
    unsigned a0, unsigned a1, unsigned a2, unsigned a3,
    unsigned b0, unsigned b1)
{
    asm volatile(
        "mma.sync.aligned.m16n8k8.row.col.f32.tf32.tf32.f32 "
        "{%0,%1,%2,%3}, {%4,%5,%6,%7}, {%8,%9}, {%0,%1,%2,%3};"
        : "+f"(c[0]), "+f"(c[1]), "+f"(c[2]), "+f"(c[3])
        : "r"(a0), "r"(a1), "r"(a2), "r"(a3), "r"(b0), "r"(b1));
}

// ---------------------------------------------------------------------------
// Pre-pass: round fp32 -> tf32-representable (unbiased rna) AND k-permute:
// out group [0..7] = in[0], in[4], in[1], in[5], in[2], in[6], in[3], in[7].
// One thread per 8-element group; fully coalesced float4 in and out.
// ---------------------------------------------------------------------------
__global__ void round_perm_k(const float* __restrict__ s, float* __restrict__ d, int n8)
{
    int i = blockIdx.x * blockDim.x + threadIdx.x;
    if (i < n8) {
        const float4* s4 = (const float4*)s + (size_t)i * 2;
        float4 i0 = s4[0], i1 = s4[1];
        float4 o0 = { roundtf(i0.x), roundtf(i1.x), roundtf(i0.y), roundtf(i1.y) };
        float4 o1 = { roundtf(i0.z), roundtf(i1.z), roundtf(i0.w), roundtf(i1.w) };
        float4* d4 = (float4*)d + (size_t)i * 2;
        d4[0] = o0; d4[1] = o1;
    }
}

// ---------------------------------------------------------------------------
// GEMM (NT) tf32: C[M,N] = A[M,K] @ B[N,K]^T + bias[N]
// A and B are K-PERMUTED in global; C written natural.
// 128x128 block, BK=16, 128 threads (4 warps), warp tile 64x64.
// 3-stage cp.async pipeline; pad 24 floats/row -> conflict-free LDS.64
// fragment loads (pairs (k,k+4) adjacent thanks to the permutation).
// ---------------------------------------------------------------------------
#define GROW 24                  // floats per smem row
#define GSTG (128 * GROW)        // floats per stage per matrix (3072)
#define GEMM_SMEM (6 * GSTG * 4) // 73728 bytes

__global__ __launch_bounds__(128) void gemm_tf32(
    const float* __restrict__ A, const float* __restrict__ B,
    const float* __restrict__ bias, float* __restrict__ C,
    int M, int N, int K, int round_out)
{
    extern __shared__ __align__(16) float sm[];
    float* As = sm;              // [3][128][24]
    float* Bs = sm + 3 * GSTG;   // [3][128][24]

    const int tid  = threadIdx.x;
    const int warp = tid >> 5;
    const int lane = tid & 31;
    const int g    = lane >> 2;
    const int tg   = lane & 3;
    const int wm   = warp >> 1;
    const int wn   = warp & 1;

    const int m0 = blockIdx.y * 128;
    const int n0 = blockIdx.x * 128;

    float acc[4][8][4];
#pragma unroll
    for (int i = 0; i < 4; i++)
#pragma unroll
        for (int j = 0; j < 8; j++)
#pragma unroll
            for (int r = 0; r < 4; r++) acc[i][j][r] = 0.f;

    const int iters = K >> 4;

#define GEMM_ISSUE(st, k0)                                                     \
    {                                                                          \
        _Pragma("unroll")                                                      \
        for (int i = 0; i < 4; i++) {                                          \
            int f  = i * 128 + tid;                                            \
            int r  = f >> 2;                                                   \
            int c4 = (f & 3) << 2;                                             \
            cp16(&As[(st) * GSTG + r * GROW + c4],                             \
                 &A[(size_t)(m0 + r) * K + (k0) + c4]);                        \
            cp16(&Bs[(st) * GSTG + r * GROW + c4],                             \
                 &B[(size_t)(n0 + r) * K + (k0) + c4]);                        \
        }                                                                      \
        CP_COMMIT();                                                           \
    }

    GEMM_ISSUE(0, 0)
    if (iters > 1) GEMM_ISSUE(1, 16)

    int buf = 0;
    for (int it = 0; it < iters; it++) {
        if (it == iters - 1) { CP_WAIT0(); } else { CP_WAIT1(); }
        __syncthreads();

        if (it + 2 < iters) {
            int nst = buf + 2; if (nst >= 3) nst -= 3;
            GEMM_ISSUE(nst, (it + 2) << 4)
        }

        const float2* A2 = (const float2*)(As + buf * GSTG);
        const float2* B2 = (const float2*)(Bs + buf * GSTG);
#pragma unroll
        for (int ks = 0; ks < 2; ks++) {
            const int kk2 = ks * 4;    // float2 offset of this k8 step
            unsigned a[4][4];
#pragma unroll
            for (int ma = 0; ma < 4; ma++) {
                int r = wm * 64 + ma * 16 + g;
                float2 p = A2[(size_t)r       * 12 + kk2 + tg];  // (a0, a2)
                float2 q = A2[(size_t)(r + 8) * 12 + kk2 + tg];  // (a1, a3)
                a[ma][0] = __float_as_uint(p.x);
                a[ma][1] = __float_as_uint(q.x);
                a[ma][2] = __float_as_uint(p.y);
                a[ma][3] = __float_as_uint(q.y);
            }
            unsigned b[8][2];
#pragma unroll
            for (int na = 0; na < 8; na++) {
                int n = wn * 64 + na * 8 + g;
                float2 bb = B2[(size_t)n * 12 + kk2 + tg];       // (b0, b1)
                b[na][0] = __float_as_uint(bb.x);
                b[na][1] = __float_as_uint(bb.y);
            }
#pragma unroll
            for (int ma = 0; ma < 4; ma++)
#pragma unroll
                for (int na = 0; na < 8; na++)
                    mma8(acc[ma][na], a[ma][0], a[ma][1], a[ma][2], a[ma][3],
                         b[na][0], b[na][1]);
        }
        buf = (buf + 1 == 3) ? 0 : buf + 1;
    }

    // Epilogue (natural layout)
#pragma unroll
    for (int ma = 0; ma < 4; ma++) {
        int row0 = m0 + wm * 64 + ma * 16 + g;
#pragma unroll
        for (int na = 0; na < 8; na++) {
            int col = n0 + wn * 64 + na * 8 + tg * 2;
            float2 bv = *(const float2*)&bias[col];
            float2 v0 = { acc[ma][na][0] + bv.x, acc[ma][na][1] + bv.y };
            float2 v1 = { acc[ma][na][2] + bv.x, acc[ma][na][3] + bv.y };
            if (round_out) {
                v0.x = roundtf(v0.x); v0.y = roundtf(v0.y);
                v1.x = roundtf(v1.x); v1.y = roundtf(v1.y);
            }
            *(float2*)&C[(size_t)row0 * N + col]       = v0;
            *(float2*)&C[(size_t)(row0 + 8) * N + col] = v1;
        }
    }
}

// ---------------------------------------------------------------------------
// Flash attention, tf32 (PROVEN R4/R10; only the final store permutes columns
// to match GEMM3's K-permuted A layout). Grid: (S/64, B*H). Block: 128.
// BQ=64, BK=32 double-buffered cp.async. Q fragments register-resident.
// 44 KB static smem.
// ---------------------------------------------------------------------------
#define OFF_K   0            // [2][32][68]  -> 4352 floats
#define OFF_V   4352         // [2][32][72]  -> 4608 floats
#define OFF_P   8960         // [64][36]     -> 2304 floats
#define SM_FLT  11264        // 45056 bytes

__global__ __launch_bounds__(128) void attn_tf32(
    const float* __restrict__ qkv, float* __restrict__ outp)
{
    __shared__ __align__(16) float smf[SM_FLT];

    const int tid  = threadIdx.x;
    const int warp = tid >> 5;
    const int lane = tid & 31;
    const int g    = lane >> 2;
    const int tg   = lane & 3;
    const int wq0  = warp * 16;

    const int qt = blockIdx.x;
    const int bh = blockIdx.y;
    const int b  = bh >> 4;
    const int h  = bh & 15;

    const size_t rowbase = (size_t)b * SEQ * QKVN;
    const int qcol = h * DHEAD;
    const int kcol = DMODEL + h * DHEAD;
    const int vcol = 2 * DMODEL + h * DHEAD;
    const int q0   = qt * 64;

    // Stage Q tile (64x64) into smem scratch, pull fragments to registers.
#pragma unroll
    for (int i = 0; i < 8; i++) {
        int f  = i * 128 + tid;
        int r  = f >> 4;
        int c4 = (f & 15) << 2;
        cp16(&smf[r * 68 + c4],
             &qkv[rowbase + (size_t)(q0 + r) * QKVN + qcol + c4]);
    }
    CP_COMMIT();
    CP_WAIT0();
    __syncthreads();

    unsigned qa[8][4];
#pragma unroll
    for (int ks = 0; ks < 8; ks++) {
        const int kk = ks * 8;
        qa[ks][0] = __float_as_uint(smf[(wq0 + g    ) * 68 + kk + tg]);
        qa[ks][1] = __float_as_uint(smf[(wq0 + g + 8) * 68 + kk + tg]);
        qa[ks][2] = __float_as_uint(smf[(wq0 + g    ) * 68 + kk + tg + 4]);
        qa[ks][3] = __float_as_uint(smf[(wq0 + g + 8) * 68 + kk + tg + 4]);
    }
    __syncthreads();

    float o[8][4];
#pragma unroll
    for (int i = 0; i < 8; i++)
#pragma unroll
        for (int j = 0; j < 4; j++) o[i][j] = 0.f;
    float mx0 = -INFINITY, mx1 = -INFINITY;
    float l0 = 0.f, l1 = 0.f;

#define ATT_ISSUE(nb, k0g)                                                     \
    {                                                                          \
        _Pragma("unroll")                                                      \
        for (int i = 0; i < 4; i++) {                                          \
            int f  = i * 128 + tid;                                            \
            int r  = f >> 4;                                                   \
            int c4 = (f & 15) << 2;                                            \
            cp16(&smf[OFF_K + (nb) * 2176 + r * 68 + c4],                      \
                 &qkv[rowbase + (size_t)((k0g) + r) * QKVN + kcol + c4]);      \
            cp16(&smf[OFF_V + (nb) * 2304 + r * 72 + c4],                      \
                 &qkv[rowbase + (size_t)((k0g) + r) * QKVN + vcol + c4]);      \
        }                                                                      \
        CP_COMMIT();                                                           \
    }

    ATT_ISSUE(0, 0)

    const int NT = SEQ / 32;
    for (int t = 0; t < NT; t++) {
        const int buf = t & 1;
        const int kbase = OFF_K + buf * 2176;
        const int vbase = OFF_V + buf * 2304;

        if (t + 1 < NT) {
            ATT_ISSUE(buf ^ 1, (t + 1) * 32)
            CP_WAIT1();
        } else {
            CP_WAIT0();
        }
        __syncthreads();

        float s[4][4];
#pragma unroll
        for (int na = 0; na < 4; na++)
#pragma unroll
            for (int r = 0; r < 4; r++) s[na][r] = 0.f;

#pragma unroll
        for (int ks = 0; ks < 8; ks++) {
            const int kk = ks * 8;
#pragma unroll
            for (int na = 0; na < 4; na++) {
                unsigned b0 = __float_as_uint(smf[kbase + (na * 8 + g) * 68 + kk + tg]);
                unsigned b1 = __float_as_uint(smf[kbase + (na * 8 + g) * 68 + kk + tg + 4]);
                mma8(s[na], qa[ks][0], qa[ks][1], qa[ks][2], qa[ks][3], b0, b1);
            }
        }

        float t0 = -INFINITY, t1 = -INFINITY;
#pragma unroll
        for (int na = 0; na < 4; na++) {
            s[na][0] *= 0.125f; s[na][1] *= 0.125f;
            s[na][2] *= 0.125f; s[na][3] *= 0.125f;
            t0 = fmaxf(t0, fmaxf(s[na][0], s[na][1]));
            t1 = fmaxf(t1, fmaxf(s[na][2], s[na][3]));
        }
        t0 = fmaxf(t0, __shfl_xor_sync(0xffffffffu, t0, 1));
        t0 = fmaxf(t0, __shfl_xor_sync(0xffffffffu, t0, 2));
        t1 = fmaxf(t1, __shfl_xor_sync(0xffffffffu, t1, 1));
        t1 = fmaxf(t1, __shfl_xor_sync(0xffffffffu, t1, 2));

        float mn0 = fmaxf(mx0, t0), mn1 = fmaxf(mx1, t1);
        float corr0 = __expf(mx0 - mn0), corr1 = __expf(mx1 - mn1);

        float ls0 = 0.f, ls1 = 0.f;
#pragma unroll
        for (int na = 0; na < 4; na++) {
            float p0 = __expf(s[na][0] - mn0);
            float p1 = __expf(s[na][1] - mn0);
            float p2 = __expf(s[na][2] - mn1);
            float p3 = __expf(s[na][3] - mn1);
            ls0 += p0 + p1; ls1 += p2 + p3;
            int c = na * 8 + tg * 2;
            smf[OFF_P + (wq0 + g    ) * 36 + c    ] = __uint_as_float(f2tf(p0));
            smf[OFF_P + (wq0 + g    ) * 36 + c + 1] = __uint_as_float(f2tf(p1));
            smf[OFF_P + (wq0 + g + 8) * 36 + c    ] = __uint_as_float(f2tf(p2));
            smf[OFF_P + (wq0 + g + 8) * 36 + c + 1] = __uint_as_float(f2tf(p3));
        }
        ls0 += __shfl_xor_sync(0xffffffffu, ls0, 1);
        ls0 += __shfl_xor_sync(0xffffffffu, ls0, 2);
        ls1 += __shfl_xor_sync(0xffffffffu, ls1, 1);
        ls1 += __shfl_xor_sync(0xffffffffu, ls1, 2);
        l0 = l0 * corr0 + ls0;  mx0 = mn0;
        l1 = l1 * corr1 + ls1;  mx1 = mn1;

#pragma unroll
        for (int na = 0; na < 8; na++) {
            o[na][0] *= corr0; o[na][1] *= corr0;
            o[na][2] *= corr1; o[na][3] *= corr1;
        }

        __syncwarp();

#pragma unroll
        for (int ks = 0; ks < 4; ks++) {
            const int kk = ks * 8;
            unsigned a0 = __float_as_uint(smf[OFF_P + (wq0 + g    ) * 36 + kk + tg]);
            unsigned a1 = __float_as_uint(smf[OFF_P + (wq0 + g + 8) * 36 + kk + tg]);
            unsigned a2 = __float_as_uint(smf[OFF_P + (wq0 + g    ) * 36 + kk + tg + 4]);
            unsigned a3 = __float_as_uint(smf[OFF_P + (wq0 + g + 8) * 36 + kk + tg + 4]);
#pragma unroll
            for (int na = 0; na < 8; na++) {
                unsigned b0 = __float_as_uint(smf[vbase + (kk + tg    ) * 72 + na * 8 + g]);
                unsigned b1 = __float_as_uint(smf[vbase + (kk + tg + 4) * 72 + na * 8 + g]);
                mma8(o[na], a0, a1, a2, a3, b0, b1);
            }
        }
        __syncthreads();
    }

    // Finalize + store to PERMUTED layout (GEMM3's A). Original cols
    // c = 8na+2tg (even) and c+1 map to 8na + pe and 8na + pe + 2,
    // pe = {0,4,1,5}[tg] (perm: p -> 2*(p%4) + (p>=4) within each 8-group).
    float inv0 = 1.0f / l0, inv1 = 1.0f / l1;
    int row0 = q0 + wq0 + g;
    size_t base0 = ((size_t)bh * SEQ + row0)     * DHEAD;
    size_t base1 = ((size_t)bh * SEQ + row0 + 8) * DHEAD;
    const int pe = (tg == 0) ? 0 : (tg == 1) ? 4 : (tg == 2) ? 1 : 5;
#pragma unroll
    for (int na = 0; na < 8; na++) {
        int cp0 = na * 8 + pe;
        outp[base0 + cp0    ] = roundtf(o[na][0] * inv0);
        outp[base0 + cp0 + 2] = roundtf(o[na][1] * inv0);
        outp[base1 + cp0    ] = roundtf(o[na][2] * inv1);
        outp[base1 + cp0 + 2] = roundtf(o[na][3] * inv1);
    }
}

// ---------------------------------------------------------------------------
// Launch
// ---------------------------------------------------------------------------
extern "C" void kernel_launch(void* const* d_in, const int* in_sizes, int n_in,
                              void* d_out, int out_size)
{
    const float* x     = (const float*)d_in[0];
    const float* w_in  = (const float*)d_in[1];
    const float* b_in  = (const float*)d_in[2];
    const float* w_out = (const float*)d_in[3];
    const float* b_out = (const float*)d_in[4];
    float* out = (float*)d_out;

    float *qkv_p, *att_p, *xr_p, *wir_p, *wor_p;
    cudaGetSymbolAddress((void**)&qkv_p, g_qkv);
    cudaGetSymbolAddress((void**)&att_p, g_att);
    cudaGetSymbolAddress((void**)&xr_p,  g_xr);
    cudaGetSymbolAddress((void**)&wir_p, g_wir);
    cudaGetSymbolAddress((void**)&wor_p, g_wor);

    cudaFuncSetAttribute(gemm_tf32,
        cudaFuncAttributeMaxDynamicSharedMemorySize, GEMM_SMEM);

    // 0) Round + k-permute inputs
    {
        int n8x  = (MROWS * DMODEL) / 8;      // 524288
        int n8wi = (QKVN * DMODEL) / 8;       // 393216
        int n8wo = (DMODEL * DMODEL) / 8;     // 131072
        round_perm_k<<<(n8x  + 255) / 256, 256>>>(x,     xr_p,  n8x);
        round_perm_k<<<(n8wi + 255) / 256, 256>>>(w_in,  wir_p, n8wi);
        round_perm_k<<<(n8wo + 255) / 256, 256>>>(w_out, wor_p, n8wo);
    }
    // 1) QKV = x @ w_in^T + b_in (natural output, rounded)
    {
        dim3 grid(QKVN / 128, MROWS / 128);
        gemm_tf32<<<grid, 128, GEMM_SMEM>>>(xr_p, wir_p, b_in, qkv_p,
                                            MROWS, QKVN, DMODEL, 1);
    }
    // 2) attention -> g_att (permuted, rounded) in [B][H][S][Dh]
    {
        dim3 grid(SEQ / 64, BATCH * NHEADS);
        attn_tf32<<<grid, 128>>>(qkv_p, att_p);
    }
    // 3) out = att @ w_out^T + b_out (natural output)
    {
        dim3 grid(DMODEL / 128, MROWS / 128);
        gemm_tf32<<<grid, 128, GEMM_SMEM>>>(att_p, wor_p, b_out, out,
                                            MROWS, DMODEL, DMODEL, 0);
    }
}

// round 12
// speedup vs baseline: 1.1595x; 1.0207x over previous
#include <cuda_runtime.h>
#include <cuda_bf16.h>
#include <math.h>
#include <stdint.h>

// Problem constants
#define BATCH   2
#define SEQ     2048
#define DMODEL  1024
#define NHEADS  16
#define DHEAD   64
#define MROWS   (BATCH * SEQ)          // 4096
#define QKVN    (3 * DMODEL)           // 3072

// K-permutation within each 8-element group: stored[j] = natural[pi(j)],
// pi = [0,4,1,5,2,6,3,7]; sigma = pi^-1 = [0,2,4,6,1,3,5,7].
// All GEMM operands AND qkv (head-dim) AND P (key-dim) use this layout so
// every mma fragment pair (k, k+4) is adjacent -> LDS.64.
__device__ float g_qkv[(size_t)MROWS * QKVN];     // head-dim permuted
__device__ float g_att[(size_t)MROWS * DMODEL];   // permuted (== GEMM3 A layout)
__device__ float g_xr [(size_t)MROWS * DMODEL];   // permuted
__device__ float g_wir[(size_t)QKVN * DMODEL];    // permuted
__device__ float g_wor[(size_t)DMODEL * DMODEL];  // permuted

// ---------------------------------------------------------------------------
// helpers
// ---------------------------------------------------------------------------
__device__ __forceinline__ unsigned f2tf(float f) {
    unsigned r;
    asm("cvt.rna.tf32.f32 %0, %1;" : "=r"(r) : "f"(f));
    return r;
}
__device__ __forceinline__ float roundtf(float f) {
    return __uint_as_float(f2tf(f));
}
__device__ __forceinline__ void cp16(void* sdst, const void* gsrc) {
    unsigned s = (unsigned)__cvta_generic_to_shared(sdst);
    asm volatile("cp.async.cg.shared.global [%0], [%1], 16;" :: "r"(s), "l"(gsrc) : "memory");
}
#define CP_COMMIT()  asm volatile("cp.async.commit_group;" ::: "memory")
#define CP_WAIT0()   asm volatile("cp.async.wait_group 0;" ::: "memory")
#define CP_WAIT1()   asm volatile("cp.async.wait_group 1;" ::: "memory")

__device__ __forceinline__ void mma8(float c[4],
    unsigned a0, unsigned a1, unsigned a2, unsigned a3,
    unsigned b0, unsigned b1)
{
    asm volatile(
        "mma.sync.aligned.m16n8k8.row.col.f32.tf32.tf32.f32 "
        "{%0,%1,%2,%3}, {%4,%5,%6,%7}, {%8,%9}, {%0,%1,%2,%3};"
        : "+f"(c[0]), "+f"(c[1]), "+f"(c[2]), "+f"(c[3])
        : "r"(a0), "r"(a1), "r"(a2), "r"(a3), "r"(b0), "r"(b1));
}

// ---------------------------------------------------------------------------
// Pre-pass: round (unbiased rna) + k-permute (out[j] = in[pi(j)] per 8-group)
// ---------------------------------------------------------------------------
__global__ void round_perm_k(const float* __restrict__ s, float* __restrict__ d, int n8)
{
    int i = blockIdx.x * blockDim.x + threadIdx.x;
    if (i < n8) {
        const float4* s4 = (const float4*)s + (size_t)i * 2;
        float4 i0 = s4[0], i1 = s4[1];
        float4 o0 = { roundtf(i0.x), roundtf(i1.x), roundtf(i0.y), roundtf(i1.y) };
        float4 o1 = { roundtf(i0.z), roundtf(i1.z), roundtf(i0.w), roundtf(i1.w) };
        float4* d4 = (float4*)d + (size_t)i * 2;
        d4[0] = o0; d4[1] = o1;
    }
}

// ---------------------------------------------------------------------------
// GEMM (NT) tf32: C[M,N] = A[M,K] @ B[N,K]^T + bias[N]
// A,B K-permuted. mode=1: round output to tf32 AND write columns sigma-
// permuted (produces permuted qkv). mode=0: plain natural fp32 output.
// 128x128 block, BK=16, 128 threads (4 warps, 64x64 each), 3-stage cp.async.
// 32-bit smem index math throughout.
// ---------------------------------------------------------------------------
#define GROW 24                  // floats per smem row
#define GSTG (128 * GROW)        // floats per stage per matrix (3072)
#define GEMM_SMEM (6 * GSTG * 4) // 73728 bytes

__global__ __launch_bounds__(128) void gemm_tf32(
    const float* __restrict__ A, const float* __restrict__ B,
    const float* __restrict__ bias, float* __restrict__ C,
    int M, int N, int K, int mode)
{
    extern __shared__ __align__(16) float sm[];
    float* As = sm;              // [3][128][24]
    float* Bs = sm + 3 * GSTG;   // [3][128][24]

    const int tid  = threadIdx.x;
    const int warp = tid >> 5;
    const int lane = tid & 31;
    const int g    = lane >> 2;
    const int tg   = lane & 3;
    const int wm   = warp >> 1;
    const int wn   = warp & 1;

    const int m0 = blockIdx.y * 128;
    const int n0 = blockIdx.x * 128;

    float acc[4][8][4];
#pragma unroll
    for (int i = 0; i < 4; i++)
#pragma unroll
        for (int j = 0; j < 8; j++)
#pragma unroll
            for (int r = 0; r < 4; r++) acc[i][j][r] = 0.f;

    const int iters = K >> 4;

#define GEMM_ISSUE(st, k0)                                                     \
    {                                                                          \
        _Pragma("unroll")                                                      \
        for (int i = 0; i < 4; i++) {                                          \
            int f  = i * 128 + tid;                                            \
            int r  = f >> 2;                                                   \
            int c4 = (f & 3) << 2;                                             \
            cp16(&As[(st) * GSTG + r * GROW + c4],                             \
                 &A[(size_t)(m0 + r) * K + (k0) + c4]);                        \
            cp16(&Bs[(st) * GSTG + r * GROW + c4],                             \
                 &B[(size_t)(n0 + r) * K + (k0) + c4]);                        \
        }                                                                      \
        CP_COMMIT();                                                           \
    }

    GEMM_ISSUE(0, 0)
    if (iters > 1) GEMM_ISSUE(1, 16)

    int buf = 0;
    for (int it = 0; it < iters; it++) {
        if (it == iters - 1) { CP_WAIT0(); } else { CP_WAIT1(); }
        __syncthreads();

        if (it + 2 < iters) {
            int nst = buf + 2; if (nst >= 3) nst -= 3;
            GEMM_ISSUE(nst, (it + 2) << 4)
        }

        const float2* A2 = (const float2*)(As + buf * GSTG);
        const float2* B2 = (const float2*)(Bs + buf * GSTG);
#pragma unroll
        for (int ks = 0; ks < 2; ks++) {
            const int kk2 = ks * 4;    // float2 offset of this k8 step
            unsigned a[4][4];
#pragma unroll
            for (int ma = 0; ma < 4; ma++) {
                int r = wm * 64 + ma * 16 + g;         // 32-bit math
                float2 p = A2[r * 12 + kk2 + tg];       // (a0, a2)
                float2 q = A2[r * 12 + 96 + kk2 + tg];  // row+8: +8*12 (a1, a3)
                a[ma][0] = __float_as_uint(p.x);
                a[ma][1] = __float_as_uint(q.x);
                a[ma][2] = __float_as_uint(p.y);
                a[ma][3] = __float_as_uint(q.y);
            }
            unsigned b[8][2];
#pragma unroll
            for (int na = 0; na < 8; na++) {
                int n = wn * 64 + na * 8 + g;
                float2 bb = B2[n * 12 + kk2 + tg];      // (b0, b1)
                b[na][0] = __float_as_uint(bb.x);
                b[na][1] = __float_as_uint(bb.y);
            }
#pragma unroll
            for (int ma = 0; ma < 4; ma++)
#pragma unroll
                for (int na = 0; na < 8; na++)
                    mma8(acc[ma][na], a[ma][0], a[ma][1], a[ma][2], a[ma][3],
                         b[na][0], b[na][1]);
        }
        buf = (buf + 1 == 3) ? 0 : buf + 1;
    }

    // Epilogue. Thread holds natural cols (8na+2tg, 8na+2tg+1), rows g/g+8.
    // sigma(2tg) / sigma(2tg+1) for the permuted-output mode:
    const int pe0 = (tg < 2) ? tg * 4     : tg * 4 - 7;
    const int pe1 = (tg < 2) ? tg * 4 + 2 : tg * 4 - 5;
#pragma unroll
    for (int ma = 0; ma < 4; ma++) {
        int row0 = m0 + wm * 64 + ma * 16 + g;
#pragma unroll
        for (int na = 0; na < 8; na++) {
            int colb = n0 + wn * 64 + na * 8;
            float bv0 = bias[colb + tg * 2];
            float bv1 = bias[colb + tg * 2 + 1];
            float v00 = acc[ma][na][0] + bv0, v01 = acc[ma][na][1] + bv1;
            float v10 = acc[ma][na][2] + bv0, v11 = acc[ma][na][3] + bv1;
            if (mode) {   // rounded + sigma-permuted scatter (qkv)
                float* r0 = &C[(size_t)row0 * N + colb];
                float* r1 = &C[(size_t)(row0 + 8) * N + colb];
                r0[pe0] = roundtf(v00); r0[pe1] = roundtf(v01);
                r1[pe0] = roundtf(v10); r1[pe1] = roundtf(v11);
            } else {      // natural vectorized (final output)
                *(float2*)&C[(size_t)row0 * N + colb + tg * 2]
                    = make_float2(v00, v01);
                *(float2*)&C[(size_t)(row0 + 8) * N + colb + tg * 2]
                    = make_float2(v10, v11);
            }
        }
    }
}

// ---------------------------------------------------------------------------
// Flash attention, tf32, head-dim-permuted qkv. Grid: (S/64, B*H). Block: 128.
// BQ=64, BK=32 double-buffered cp.async. Q fragments register-resident.
// K fragments + P fragments load as float2 (permuted pairing); V scalar.
// Output = O in permuted-dim order == GEMM3's expected A layout (plain
// vectorized stores). 46 KB static smem.
// Layout (floats): K dbuf 2x32x72 @0 ; V dbuf 2x32x72 @4608 ; P 64x40 @9216.
// Q staged temporarily at 0 (64x72 = 4608 = K dbuf region).
// ---------------------------------------------------------------------------
#define OFF_K   0
#define OFF_V   4608
#define OFF_P   9216
#define SM_FLT  11776        // 47104 bytes

__global__ __launch_bounds__(128) void attn_tf32(
    const float* __restrict__ qkv, float* __restrict__ outp)
{
    __shared__ __align__(16) float smf[SM_FLT];

    const int tid  = threadIdx.x;
    const int warp = tid >> 5;
    const int lane = tid & 31;
    const int g    = lane >> 2;
    const int tg   = lane & 3;
    const int wq0  = warp * 16;

    const int qt = blockIdx.x;
    const int bh = blockIdx.y;
    const int b  = bh >> 4;
    const int h  = bh & 15;

    const size_t rowbase = (size_t)b * SEQ * QKVN;
    const int qcol = h * DHEAD;
    const int kcol = DMODEL + h * DHEAD;
    const int vcol = 2 * DMODEL + h * DHEAD;
    const int q0   = qt * 64;

    // --- Stage Q tile (64 rows x 64 floats, stride 72) then pull fragments ---
#pragma unroll
    for (int i = 0; i < 8; i++) {
        int f  = i * 128 + tid;
        int r  = f >> 4;
        int c4 = (f & 15) << 2;
        cp16(&smf[r * 72 + c4],
             &qkv[rowbase + (size_t)(q0 + r) * QKVN + qcol + c4]);
    }
    CP_COMMIT();
    CP_WAIT0();
    __syncthreads();

    unsigned qa[8][4];
    {
        const float2* Q2 = (const float2*)smf;
#pragma unroll
        for (int ks = 0; ks < 8; ks++) {
            float2 p = Q2[(wq0 + g    ) * 36 + ks * 4 + tg];   // (a0, a2)
            float2 q = Q2[(wq0 + g + 8) * 36 + ks * 4 + tg];   // (a1, a3)
            qa[ks][0] = __float_as_uint(p.x);
            qa[ks][1] = __float_as_uint(q.x);
            qa[ks][2] = __float_as_uint(p.y);
            qa[ks][3] = __float_as_uint(q.y);
        }
    }
    __syncthreads();   // Q reads done before K prefetch overwrites region

    float o[8][4];
#pragma unroll
    for (int i = 0; i < 8; i++)
#pragma unroll
        for (int j = 0; j < 4; j++) o[i][j] = 0.f;
    float mx0 = -INFINITY, mx1 = -INFINITY;
    float l0 = 0.f, l1 = 0.f;

    // sigma positions for P stores (thread's natural keys 2tg, 2tg+1)
    const int pe0 = (tg < 2) ? tg * 4     : tg * 4 - 7;
    const int pe1 = (tg < 2) ? tg * 4 + 2 : tg * 4 - 5;

#define ATT_ISSUE(nb, k0g)                                                     \
    {                                                                          \
        _Pragma("unroll")                                                      \
        for (int i = 0; i < 4; i++) {                                          \
            int f  = i * 128 + tid;                                            \
            int r  = f >> 4;                                                   \
            int c4 = (f & 15) << 2;                                            \
            cp16(&smf[OFF_K + (nb) * 2304 + r * 72 + c4],                      \
                 &qkv[rowbase + (size_t)((k0g) + r) * QKVN + kcol + c4]);      \
            cp16(&smf[OFF_V + (nb) * 2304 + r * 72 + c4],                      \
                 &qkv[rowbase + (size_t)((k0g) + r) * QKVN + vcol + c4]);      \
        }                                                                      \
        CP_COMMIT();                                                           \
    }

    ATT_ISSUE(0, 0)

    const int NT = SEQ / 32;
    for (int t = 0; t < NT; t++) {
        const int buf = t & 1;

        if (t + 1 < NT) {
            ATT_ISSUE(buf ^ 1, (t + 1) * 32)
            CP_WAIT1();
        } else {
            CP_WAIT0();
        }
        __syncthreads();

        const float2* K2 = (const float2*)(smf + OFF_K + buf * 2304);
        const float*  Vs = smf + OFF_V + buf * 2304;

        // --- Scores: S[16q x 32k] = Q @ K^T (float2 K fragments) ---
        float s[4][4];
#pragma unroll
        for (int na = 0; na < 4; na++)
#pragma unroll
            for (int r = 0; r < 4; r++) s[na][r] = 0.f;

#pragma unroll
        for (int ks = 0; ks < 8; ks++) {
            const int kk2 = ks * 4;
#pragma unroll
            for (int na = 0; na < 4; na++) {
                float2 bb = K2[(na * 8 + g) * 36 + kk2 + tg];
                mma8(s[na], qa[ks][0], qa[ks][1], qa[ks][2], qa[ks][3],
                     __float_as_uint(bb.x), __float_as_uint(bb.y));
            }
        }

        // --- Online softmax (rows g / g+8, quad shfl reduce) ---
        float t0 = -INFINITY, t1 = -INFINITY;
#pragma unroll
        for (int na = 0; na < 4; na++) {
            s[na][0] *= 0.125f; s[na][1] *= 0.125f;
            s[na][2] *= 0.125f; s[na][3] *= 0.125f;
            t0 = fmaxf(t0, fmaxf(s[na][0], s[na][1]));
            t1 = fmaxf(t1, fmaxf(s[na][2], s[na][3]));
        }
        t0 = fmaxf(t0, __shfl_xor_sync(0xffffffffu, t0, 1));
        t0 = fmaxf(t0, __shfl_xor_sync(0xffffffffu, t0, 2));
        t1 = fmaxf(t1, __shfl_xor_sync(0xffffffffu, t1, 1));
        t1 = fmaxf(t1, __shfl_xor_sync(0xffffffffu, t1, 2));

        float mn0 = fmaxf(mx0, t0), mn1 = fmaxf(mx1, t1);
        float corr0 = __expf(mx0 - mn0), corr1 = __expf(mx1 - mn1);

        float ls0 = 0.f, ls1 = 0.f;
        {
            float* Pr0 = smf + OFF_P + (wq0 + g    ) * 40;
            float* Pr1 = smf + OFF_P + (wq0 + g + 8) * 40;
#pragma unroll
            for (int na = 0; na < 4; na++) {
                float p0 = __expf(s[na][0] - mn0);
                float p1 = __expf(s[na][1] - mn0);
                float p2 = __expf(s[na][2] - mn1);
                float p3 = __expf(s[na][3] - mn1);
                ls0 += p0 + p1; ls1 += p2 + p3;
                int cb = na * 8;
                Pr0[cb + pe0] = roundtf(p0); Pr0[cb + pe1] = roundtf(p1);
                Pr1[cb + pe0] = roundtf(p2); Pr1[cb + pe1] = roundtf(p3);
            }
        }
        ls0 += __shfl_xor_sync(0xffffffffu, ls0, 1);
        ls0 += __shfl_xor_sync(0xffffffffu, ls0, 2);
        ls1 += __shfl_xor_sync(0xffffffffu, ls1, 1);
        ls1 += __shfl_xor_sync(0xffffffffu, ls1, 2);
        l0 = l0 * corr0 + ls0;  mx0 = mn0;
        l1 = l1 * corr1 + ls1;  mx1 = mn1;

#pragma unroll
        for (int na = 0; na < 8; na++) {
            o[na][0] *= corr0; o[na][1] *= corr0;
            o[na][2] *= corr1; o[na][3] *= corr1;
        }

        __syncwarp();   // P rows warp-private: order STS -> LDS

        // --- PV: O[16q x 64d] += P[16x32] @ V[32x64] (float2 P fragments) ---
        {
            const float2* P2 = (const float2*)(smf + OFF_P);
#pragma unroll
            for (int ks = 0; ks < 4; ks++) {
                const int kk = ks * 8;
                float2 pa = P2[(wq0 + g    ) * 20 + ks * 4 + tg];
                float2 pb = P2[(wq0 + g + 8) * 20 + ks * 4 + tg];
                unsigned a0 = __float_as_uint(pa.x);
                unsigned a1 = __float_as_uint(pb.x);
                unsigned a2 = __float_as_uint(pa.y);
                unsigned a3 = __float_as_uint(pb.y);
#pragma unroll
                for (int na = 0; na < 8; na++) {
                    int n = na * 8 + g;
                    unsigned b0 = __float_as_uint(Vs[(kk + tg    ) * 72 + n]);
                    unsigned b1 = __float_as_uint(Vs[(kk + tg + 4) * 72 + n]);
                    mma8(o[na], a0, a1, a2, a3, b0, b1);
                }
            }
        }
        __syncthreads();   // all warps done with buf before next overwrite
    }

    // --- Finalize + store. O columns are permuted-V dims == exactly the
    //     k-permuted layout GEMM3 expects: plain vectorized stores. ---
    float inv0 = 1.0f / l0, inv1 = 1.0f / l1;
    int row0 = q0 + wq0 + g;
    size_t base0 = ((size_t)bh * SEQ + row0)     * DHEAD;
    size_t base1 = ((size_t)bh * SEQ + row0 + 8) * DHEAD;
#pragma unroll
    for (int na = 0; na < 8; na++) {
        int c = na * 8 + tg * 2;
        float2 v0 = { roundtf(o[na][0] * inv0), roundtf(o[na][1] * inv0) };
        float2 v1 = { roundtf(o[na][2] * inv1), roundtf(o[na][3] * inv1) };
        *(float2*)&outp[base0 + c] = v0;
        *(float2*)&outp[base1 + c] = v1;
    }
}

// ---------------------------------------------------------------------------
// Launch
// ---------------------------------------------------------------------------
extern "C" void kernel_launch(void* const* d_in, const int* in_sizes, int n_in,
                              void* d_out, int out_size)
{
    const float* x     = (const float*)d_in[0];
    const float* w_in  = (const float*)d_in[1];
    const float* b_in  = (const float*)d_in[2];
    const float* w_out = (const float*)d_in[3];
    const float* b_out = (const float*)d_in[4];
    float* out = (float*)d_out;

    float *qkv_p, *att_p, *xr_p, *wir_p, *wor_p;
    cudaGetSymbolAddress((void**)&qkv_p, g_qkv);
    cudaGetSymbolAddress((void**)&att_p, g_att);
    cudaGetSymbolAddress((void**)&xr_p,  g_xr);
    cudaGetSymbolAddress((void**)&wir_p, g_wir);
    cudaGetSymbolAddress((void**)&wor_p, g_wor);

    cudaFuncSetAttribute(gemm_tf32,
        cudaFuncAttributeMaxDynamicSharedMemorySize, GEMM_SMEM);

    // 0) Round + k-permute inputs
    {
        int n8x  = (MROWS * DMODEL) / 8;
        int n8wi = (QKVN * DMODEL) / 8;
        int n8wo = (DMODEL * DMODEL) / 8;
        round_perm_k<<<(n8x  + 255) / 256, 256>>>(x,     xr_p,  n8x);
        round_perm_k<<<(n8wi + 255) / 256, 256>>>(w_in,  wir_p, n8wi);
        round_perm_k<<<(n8wo + 255) / 256, 256>>>(w_out, wor_p, n8wo);
    }
    // 1) QKV = x @ w_in^T + b_in  (mode=1: rounded + sigma-permuted columns)
    {
        dim3 grid(QKVN / 128, MROWS / 128);
        gemm_tf32<<<grid, 128, GEMM_SMEM>>>(xr_p, wir_p, b_in, qkv_p,
                                            MROWS, QKVN, DMODEL, 1);
    }
    // 2) attention (permuted-dim qkv) -> g_att (permuted) in [B][H][S][Dh]
    {
        dim3 grid(SEQ / 64, BATCH * NHEADS);
        attn_tf32<<<grid, 128>>>(qkv_p, att_p);
    }
    // 3) out = att @ w_out^T + b_out (mode=0: natural fp32 output)
    {
        dim3 grid(DMODEL / 128, MROWS / 128);
        gemm_tf32<<<grid, 128, GEMM_SMEM>>>(att_p, wor_p, b_out, out,
                                            MROWS, DMODEL, DMODEL, 0);
    }
}